// round 14
// baseline (speedup 1.0000x reference)
#include <cuda_runtime.h>
#include <cuda_fp16.h>
#include <cstdint>
#include <cstddef>

#define NN 100000
#define EE 500000
#define MROWS 200000
#define MTILES 1563  // ceil(200000/128)

// Per-node first-layer tables in fp16 (102.4 MB -> mostly L2-resident).
// P[n, 0:128] = z_pnode[n] @ w1_top ; P[n, 128:256] = z_pnode[n] @ w1_bot + b1
__device__ __half g_P[(size_t)NN * 256];
__device__ __half g_O[(size_t)NN * 256];

__device__ __forceinline__ void mma_f16(float* d, const uint32_t* a,
                                        const uint32_t* b) {
  asm volatile(
      "mma.sync.aligned.m16n8k16.row.col.f32.f16.f16.f32 "
      "{%0,%1,%2,%3}, {%4,%5,%6,%7}, {%8,%9}, {%0,%1,%2,%3};"
      : "+f"(d[0]), "+f"(d[1]), "+f"(d[2]), "+f"(d[3])
      : "r"(a[0]), "r"(a[1]), "r"(a[2]), "r"(a[3]), "r"(b[0]), "r"(b[1]));
}

__device__ __forceinline__ void cp16(void* smem_dst, const void* gmem_src) {
  uint32_t s = (uint32_t)__cvta_generic_to_shared(smem_dst);
  asm volatile("cp.async.cg.shared.global [%0], [%1], 16;" ::"r"(s),
               "l"(gmem_src));
}

__device__ __forceinline__ uint32_t pack_h2(float lo, float hi) {
  __half2 h = __floats2half2_rn(lo, hi);
  return *(uint32_t*)&h;
}

#define BS_LD2 264  // half2 per B pair-row (1056B; %128==32B -> conflict-free)
#define AS_LDF 132  // fp32 per A row (528B; words%32==4 -> conflict-free)
#define CS_LDH 264  // halves per staged C row (528B) == A row bytes
#define B_BYTES (64 * BS_LD2 * 4)           // 67584
#define A_BYTES (128 * AS_LDF * 4)          // 67584 (== 128*CS_LDH*2)
#define SMEM_TOTAL (B_BYTES + 2 * A_BYTES)  // 202752

// ---------------------------------------------------------------------------
// Fused persistent fp16 GEMM (R6/R12-proven, 62.7us): C = Z @ [w1t | w1b]
// (+b1 on bot). 148 CTAs x 256 threads; CTA tile 128x256; fp32 A double-
// buffered via cp.async; fp16 B resident; C staged in smem for coalesced
// row stores. 8 warps, warp tile 64x64.
// ---------------------------------------------------------------------------
__global__ void __launch_bounds__(256, 1) gemm_kernel(
    const float* __restrict__ zp, const float* __restrict__ zo,
    const float* __restrict__ w1, const float* __restrict__ b1) {
  extern __shared__ char smem_raw[];
  __half2* Bsh = (__half2*)smem_raw;  // [64 pair-rows][BS_LD2]
  char* Abase = smem_raw + B_BYTES;   // 2 x (A fp32 tile | C half stage)
  const int tid = threadIdx.x;

  // A tile async load: 4096 x 16B fp32 chunks, 16 per thread.
  auto issueA = [&](int tile, int buf) {
    char* dst = Abase + buf * A_BYTES;
    int row0 = tile * 128;
#pragma unroll
    for (int j = 0; j < 16; j++) {
      int s = tid + 256 * j;
      int r = s >> 5;
      int c4 = s & 31;
      int grow = row0 + r;
      if (grow > MROWS - 1) grow = MROWS - 1;
      const float* src = (grow < NN) ? (zp + (size_t)grow * 128)
                                     : (zo + (size_t)(grow - NN) * 128);
      cp16(dst + r * (AS_LDF * 4) + c4 * 16, src + c4 * 4);
    }
  };

  int t = blockIdx.x;
  issueA(t, 0);
  asm volatile("cp.async.commit_group;" ::: "memory");

  // One-time B fill: fp32 w1 -> fp16 [pair p][nn], half2=(w1[2p+..][c], w1[2p+1+..][c])
  {
    const float4* w4 = (const float4*)w1;
#pragma unroll
    for (int j = 0; j < 16; j++) {
      int slot = tid + 256 * j;  // 4096 slots
      int c4 = slot & 31;
      int p = (slot >> 5) & 63;
      int hh = slot >> 11;  // 0: top cols, 1: bot cols
      float4 fa = w4[(2 * p + hh * 128) * 32 + c4];
      float4 fb = w4[(2 * p + 1 + hh * 128) * 32 + c4];
      uint4 v;
      v.x = pack_h2(fa.x, fb.x);
      v.y = pack_h2(fa.y, fb.y);
      v.z = pack_h2(fa.z, fb.z);
      v.w = pack_h2(fa.w, fb.w);
      *(uint4*)((char*)Bsh + p * (BS_LD2 * 4) + (hh * 128 + c4 * 4) * 4) = v;
    }
  }

  const int lane = tid & 31;
  const int wid = tid >> 5;
  const int g = lane >> 2;
  const int tg = lane & 3;
  const int wm = wid & 1;
  const int wn = wid >> 1;
  const int arow = wm * 64;
  const int bcol = wn * 64;
  const bool bot = (bcol >= 128);

  // Hoist per-thread b1 pairs (columns fixed across tiles).
  float2 bb[8];
  if (bot) {
#pragma unroll
    for (int ni = 0; ni < 8; ni++)
      bb[ni] = *(const float2*)(b1 + (bcol - 128) + ni * 8 + tg * 2);
  }

  int buf = 0;
  while (true) {
    int tn = t + gridDim.x;
    bool more = (tn < MTILES);
    if (more) issueA(tn, buf ^ 1);
    asm volatile("cp.async.commit_group;" ::: "memory");
    asm volatile("cp.async.wait_group 1;" ::: "memory");
    __syncthreads();

    const float* A = (const float*)(Abase + buf * A_BYTES);
    float acc[4][8][4];
#pragma unroll
    for (int mi = 0; mi < 4; mi++)
#pragma unroll
      for (int ni = 0; ni < 8; ni++)
#pragma unroll
        for (int q = 0; q < 4; q++) acc[mi][ni][q] = 0.f;

#pragma unroll
    for (int k0 = 0; k0 < 128; k0 += 16) {
      int hp = k0 >> 1;
      uint32_t bf[8][2];
#pragma unroll
      for (int ni = 0; ni < 8; ni++) {
        int col = bcol + ni * 8 + g;
        bf[ni][0] = *(const uint32_t*)&Bsh[(hp + tg) * BS_LD2 + col];
        bf[ni][1] = *(const uint32_t*)&Bsh[(hp + 4 + tg) * BS_LD2 + col];
      }
#pragma unroll
      for (int mi = 0; mi < 4; mi++) {
        int rb = arow + mi * 16 + g;
        uint32_t af[4];
        {
          float2 v = *(const float2*)&A[rb * AS_LDF + k0 + 2 * tg];
          af[0] = pack_h2(v.x, v.y);
        }
        {
          float2 v = *(const float2*)&A[(rb + 8) * AS_LDF + k0 + 2 * tg];
          af[1] = pack_h2(v.x, v.y);
        }
        {
          float2 v = *(const float2*)&A[rb * AS_LDF + k0 + 8 + 2 * tg];
          af[2] = pack_h2(v.x, v.y);
        }
        {
          float2 v = *(const float2*)&A[(rb + 8) * AS_LDF + k0 + 8 + 2 * tg];
          af[3] = pack_h2(v.x, v.y);
        }
#pragma unroll
        for (int ni = 0; ni < 8; ni++) mma_f16(acc[mi][ni], af, bf[ni]);
      }
    }

    // Stage C into this A buffer (fully consumed), then coalesced row stores.
    __syncthreads();
    __half* Cs = (__half*)(Abase + buf * A_BYTES);
#pragma unroll
    for (int mi = 0; mi < 4; mi++) {
#pragma unroll
      for (int hf = 0; hf < 2; hf++) {
        int r = wm * 64 + mi * 16 + hf * 8 + g;
#pragma unroll
        for (int ni = 0; ni < 8; ni++) {
          int c = bcol + ni * 8 + tg * 2;
          float v0 = acc[mi][ni][hf * 2];
          float v1 = acc[mi][ni][hf * 2 + 1];
          if (bot) {
            v0 += bb[ni].x;
            v1 += bb[ni].y;
          }
          *(__half2*)(Cs + r * CS_LDH + c) = __floats2half2_rn(v0, v1);
        }
      }
    }
    __syncthreads();
    int row0 = t * 128;
#pragma unroll
    for (int j = 0; j < 16; j++) {
      int slot = tid + 256 * j;  // 128 rows x 32 uint4
      int r = slot >> 5;
      int c4 = slot & 31;
      int grow = row0 + r;
      if (grow < MROWS) {
        uint4 v = *(const uint4*)(Cs + r * CS_LDH + c4 * 8);
        __half* tab = (grow < NN) ? (g_P + (size_t)grow * 256)
                                  : (g_O + (size_t)(grow - NN) * 256);
        *(uint4*)(tab + c4 * 8) = v;
      }
    }
    __syncthreads();
    if (!more) break;
    t = tn;
    buf ^= 1;
  }
}

// ---------------------------------------------------------------------------
// Edge pass v3: gridDim.y = edge type -> idx/table base pointers are
// loop-invariant (no per-iteration type logic). Persistent warps, 2 edges
// per warp-iteration (16-lane halves), half2 math, index prefetch.
// out[e] = relu(tabS[src,0:128] + tabD[dst,128:256]) . w2 + b2
// ---------------------------------------------------------------------------
#define PT (EE / 2)  // 250000 pairs per type
__global__ void __launch_bounds__(256) edge_kernel(
    const int* __restrict__ e0, const int* __restrict__ e1,
    const int* __restrict__ e2, const float* __restrict__ w2,
    const float* __restrict__ b2, float* __restrict__ out) {
  const int t = blockIdx.y;
  const int* __restrict__ idx = (t == 0) ? e0 : (t == 1) ? e1 : e2;
  const __half* __restrict__ stab = (t == 0) ? g_P : g_O;
  const __half* __restrict__ dtab = ((t == 1) ? g_P : g_O) + 128;
  float* __restrict__ outt = out + t * EE;

  const int lane = threadIdx.x & 31;
  const int h = lane >> 4;
  const int l = lane & 15;
  const int warpId = (blockIdx.x * 256 + threadIdx.x) >> 5;
  const int W = gridDim.x * 8;

  // Per-lane second-layer weights (features l*8 .. l*8+7) in half2.
  const float4 wa = ((const float4*)w2)[l * 2];
  const float4 wb = ((const float4*)w2)[l * 2 + 1];
  const __half2 w01 = __floats2half2_rn(wa.x, wa.y);
  const __half2 w23 = __floats2half2_rn(wa.z, wa.w);
  const __half2 w45 = __floats2half2_rn(wb.x, wb.y);
  const __half2 w67 = __floats2half2_rn(wb.z, wb.w);
  const __half2 z2 = __float2half2_rn(0.f);
  const float b2v = b2[0];

  int p = warpId;
  if (p >= PT) return;
  int ei = 2 * p + h;
  int s = __ldg(idx + ei);
  int d = __ldg(idx + EE + ei);

  while (true) {
    const __half* srow = stab + (unsigned)s * 256u;
    const __half* drow = dtab + (unsigned)d * 256u;
    uint4 sa = __ldg((const uint4*)srow + l);
    uint4 da = __ldg((const uint4*)drow + l);
    int ecur = ei;

    // Prefetch next iteration's indices.
    int np = p + W;
    bool more = (np < PT);
    int ns, nd;
    if (more) {
      int nei = 2 * np + h;
      ns = __ldg(idx + nei);
      nd = __ldg(idx + EE + nei);
      ei = nei;
    }

    __half2 h0 = __hmax2(__hadd2(*(__half2*)&sa.x, *(__half2*)&da.x), z2);
    __half2 h1 = __hmax2(__hadd2(*(__half2*)&sa.y, *(__half2*)&da.y), z2);
    __half2 h2 = __hmax2(__hadd2(*(__half2*)&sa.z, *(__half2*)&da.z), z2);
    __half2 h3 = __hmax2(__hadd2(*(__half2*)&sa.w, *(__half2*)&da.w), z2);
    __half2 pa = __hfma2(h1, w23, __hmul2(h0, w01));
    __half2 pb = __hfma2(h3, w67, __hmul2(h2, w45));
    float2 fa = __half22float2(pa);
    float2 fb = __half22float2(pb);
    float acc = (fa.x + fa.y) + (fb.x + fb.y);
#pragma unroll
    for (int o = 8; o; o >>= 1) acc += __shfl_xor_sync(0xffffffffu, acc, o);
    if (l == 0) outt[ecur] = acc + b2v;

    if (!more) break;
    p = np;
    s = ns;
    d = nd;
  }
}

extern "C" void kernel_launch(void* const* d_in, const int* in_sizes, int n_in,
                              void* d_out, int out_size) {
  const float* zp = (const float*)d_in[0];
  const float* zo = (const float*)d_in[1];
  const int* e0 = (const int*)d_in[2];
  const int* e1 = (const int*)d_in[3];
  const int* e2 = (const int*)d_in[4];
  const float* w1 = (const float*)d_in[5];
  const float* b1 = (const float*)d_in[6];
  const float* w2 = (const float*)d_in[7];
  const float* b2 = (const float*)d_in[8];

  cudaFuncSetAttribute(gemm_kernel,
                       cudaFuncAttributeMaxDynamicSharedMemorySize, SMEM_TOTAL);
  gemm_kernel<<<148, 256, SMEM_TOTAL>>>(zp, zo, w1, b1);

  edge_kernel<<<dim3(400, 3), 256>>>(e0, e1, e2, w2, b2, (float*)d_out);
}

// round 15
// speedup vs baseline: 1.3190x; 1.3190x over previous
#include <cuda_runtime.h>
#include <cuda_fp16.h>
#include <cstdint>
#include <cstddef>

#define NN 100000
#define EE 500000
#define MROWS 200000
#define MTILES 1563  // ceil(200000/128)

// Per-node first-layer tables in fp16 (102.4 MB -> mostly L2-resident).
// P[n, 0:128] = z_pnode[n] @ w1_top ; P[n, 128:256] = z_pnode[n] @ w1_bot + b1
__device__ __half g_P[(size_t)NN * 256];
__device__ __half g_O[(size_t)NN * 256];

__device__ __forceinline__ void mma_f16(float* d, const uint32_t* a,
                                        const uint32_t* b) {
  asm volatile(
      "mma.sync.aligned.m16n8k16.row.col.f32.f16.f16.f32 "
      "{%0,%1,%2,%3}, {%4,%5,%6,%7}, {%8,%9}, {%0,%1,%2,%3};"
      : "+f"(d[0]), "+f"(d[1]), "+f"(d[2]), "+f"(d[3])
      : "r"(a[0]), "r"(a[1]), "r"(a[2]), "r"(a[3]), "r"(b[0]), "r"(b[1]));
}

__device__ __forceinline__ void cp16(void* smem_dst, const void* gmem_src) {
  uint32_t s = (uint32_t)__cvta_generic_to_shared(smem_dst);
  asm volatile("cp.async.cg.shared.global [%0], [%1], 16;" ::"r"(s),
               "l"(gmem_src));
}

__device__ __forceinline__ uint32_t pack_h2(float lo, float hi) {
  __half2 h = __floats2half2_rn(lo, hi);
  return *(uint32_t*)&h;
}

#define BS_LD2 264  // half2 per B pair-row (1056B; %128==32B -> conflict-free)
#define AS_LDF 132  // fp32 per A row (528B; words%32==4 -> conflict-free)
#define CS_LDH 264  // halves per staged C row (528B) == A row bytes
#define B_BYTES (64 * BS_LD2 * 4)           // 67584
#define A_BYTES (128 * AS_LDF * 4)          // 67584 (== 128*CS_LDH*2)
#define SMEM_TOTAL (B_BYTES + 2 * A_BYTES)  // 202752

// ---------------------------------------------------------------------------
// Fused persistent fp16 GEMM (R6/R12-proven, 62.7us): C = Z @ [w1t | w1b]
// (+b1 on bot). 148 CTAs x 256 threads; CTA tile 128x256; fp32 A double-
// buffered via cp.async; fp16 B resident; C staged in smem for coalesced
// row stores. 8 warps, warp tile 64x64.
// ---------------------------------------------------------------------------
__global__ void __launch_bounds__(256, 1) gemm_kernel(
    const float* __restrict__ zp, const float* __restrict__ zo,
    const float* __restrict__ w1, const float* __restrict__ b1) {
  extern __shared__ char smem_raw[];
  __half2* Bsh = (__half2*)smem_raw;  // [64 pair-rows][BS_LD2]
  char* Abase = smem_raw + B_BYTES;   // 2 x (A fp32 tile | C half stage)
  const int tid = threadIdx.x;

  // A tile async load: 4096 x 16B fp32 chunks, 16 per thread.
  auto issueA = [&](int tile, int buf) {
    char* dst = Abase + buf * A_BYTES;
    int row0 = tile * 128;
#pragma unroll
    for (int j = 0; j < 16; j++) {
      int s = tid + 256 * j;
      int r = s >> 5;
      int c4 = s & 31;
      int grow = row0 + r;
      if (grow > MROWS - 1) grow = MROWS - 1;
      const float* src = (grow < NN) ? (zp + (size_t)grow * 128)
                                     : (zo + (size_t)(grow - NN) * 128);
      cp16(dst + r * (AS_LDF * 4) + c4 * 16, src + c4 * 4);
    }
  };

  int t = blockIdx.x;
  issueA(t, 0);
  asm volatile("cp.async.commit_group;" ::: "memory");

  // One-time B fill: fp32 w1 -> fp16 [pair p][nn], half2=(w1[2p+..][c], w1[2p+1+..][c])
  {
    const float4* w4 = (const float4*)w1;
#pragma unroll
    for (int j = 0; j < 16; j++) {
      int slot = tid + 256 * j;  // 4096 slots
      int c4 = slot & 31;
      int p = (slot >> 5) & 63;
      int hh = slot >> 11;  // 0: top cols, 1: bot cols
      float4 fa = w4[(2 * p + hh * 128) * 32 + c4];
      float4 fb = w4[(2 * p + 1 + hh * 128) * 32 + c4];
      uint4 v;
      v.x = pack_h2(fa.x, fb.x);
      v.y = pack_h2(fa.y, fb.y);
      v.z = pack_h2(fa.z, fb.z);
      v.w = pack_h2(fa.w, fb.w);
      *(uint4*)((char*)Bsh + p * (BS_LD2 * 4) + (hh * 128 + c4 * 4) * 4) = v;
    }
  }

  const int lane = tid & 31;
  const int wid = tid >> 5;
  const int g = lane >> 2;
  const int tg = lane & 3;
  const int wm = wid & 1;
  const int wn = wid >> 1;
  const int arow = wm * 64;
  const int bcol = wn * 64;
  const bool bot = (bcol >= 128);

  // Hoist per-thread b1 pairs (columns fixed across tiles).
  float2 bb[8];
  if (bot) {
#pragma unroll
    for (int ni = 0; ni < 8; ni++)
      bb[ni] = *(const float2*)(b1 + (bcol - 128) + ni * 8 + tg * 2);
  }

  int buf = 0;
  while (true) {
    int tn = t + gridDim.x;
    bool more = (tn < MTILES);
    if (more) issueA(tn, buf ^ 1);
    asm volatile("cp.async.commit_group;" ::: "memory");
    asm volatile("cp.async.wait_group 1;" ::: "memory");
    __syncthreads();

    const float* A = (const float*)(Abase + buf * A_BYTES);
    float acc[4][8][4];
#pragma unroll
    for (int mi = 0; mi < 4; mi++)
#pragma unroll
      for (int ni = 0; ni < 8; ni++)
#pragma unroll
        for (int q = 0; q < 4; q++) acc[mi][ni][q] = 0.f;

#pragma unroll
    for (int k0 = 0; k0 < 128; k0 += 16) {
      int hp = k0 >> 1;
      uint32_t bf[8][2];
#pragma unroll
      for (int ni = 0; ni < 8; ni++) {
        int col = bcol + ni * 8 + g;
        bf[ni][0] = *(const uint32_t*)&Bsh[(hp + tg) * BS_LD2 + col];
        bf[ni][1] = *(const uint32_t*)&Bsh[(hp + 4 + tg) * BS_LD2 + col];
      }
#pragma unroll
      for (int mi = 0; mi < 4; mi++) {
        int rb = arow + mi * 16 + g;
        uint32_t af[4];
        {
          float2 v = *(const float2*)&A[rb * AS_LDF + k0 + 2 * tg];
          af[0] = pack_h2(v.x, v.y);
        }
        {
          float2 v = *(const float2*)&A[(rb + 8) * AS_LDF + k0 + 2 * tg];
          af[1] = pack_h2(v.x, v.y);
        }
        {
          float2 v = *(const float2*)&A[rb * AS_LDF + k0 + 8 + 2 * tg];
          af[2] = pack_h2(v.x, v.y);
        }
        {
          float2 v = *(const float2*)&A[(rb + 8) * AS_LDF + k0 + 8 + 2 * tg];
          af[3] = pack_h2(v.x, v.y);
        }
#pragma unroll
        for (int ni = 0; ni < 8; ni++) mma_f16(acc[mi][ni], af, bf[ni]);
      }
    }

    // Stage C into this A buffer (fully consumed), then coalesced row stores.
    __syncthreads();
    __half* Cs = (__half*)(Abase + buf * A_BYTES);
#pragma unroll
    for (int mi = 0; mi < 4; mi++) {
#pragma unroll
      for (int hf = 0; hf < 2; hf++) {
        int r = wm * 64 + mi * 16 + hf * 8 + g;
#pragma unroll
        for (int ni = 0; ni < 8; ni++) {
          int c = bcol + ni * 8 + tg * 2;
          float v0 = acc[mi][ni][hf * 2];
          float v1 = acc[mi][ni][hf * 2 + 1];
          if (bot) {
            v0 += bb[ni].x;
            v1 += bb[ni].y;
          }
          *(__half2*)(Cs + r * CS_LDH + c) = __floats2half2_rn(v0, v1);
        }
      }
    }
    __syncthreads();
    int row0 = t * 128;
#pragma unroll
    for (int j = 0; j < 16; j++) {
      int slot = tid + 256 * j;  // 128 rows x 32 uint4
      int r = slot >> 5;
      int c4 = slot & 31;
      int grow = row0 + r;
      if (grow < MROWS) {
        uint4 v = *(const uint4*)(Cs + r * CS_LDH + c4 * 8);
        __half* tab = (grow < NN) ? (g_P + (size_t)grow * 256)
                                  : (g_O + (size_t)(grow - NN) * 256);
        *(uint4*)(tab + c4 * 8) = v;
      }
    }
    __syncthreads();
    if (!more) break;
    t = tn;
    buf ^= 1;
  }
}

// ---------------------------------------------------------------------------
// Edge pass v4: gridDim.y = edge type (loop-invariant bases) with
// __launch_bounds__(256, 8) forcing regs <= 32 to keep occupancy high.
// Persistent warps, 2 edges per warp-iteration (16-lane halves), half2 math,
// index prefetch. out[e] = relu(tabS[src,0:128] + tabD[dst,128:256]).w2 + b2
// ---------------------------------------------------------------------------
#define PT (EE / 2)  // 250000 pairs per type
__global__ void __launch_bounds__(256, 8) edge_kernel(
    const int* __restrict__ e0, const int* __restrict__ e1,
    const int* __restrict__ e2, const float* __restrict__ w2,
    const float* __restrict__ b2, float* __restrict__ out) {
  const int t = blockIdx.y;
  const int* __restrict__ idx = (t == 0) ? e0 : (t == 1) ? e1 : e2;
  const __half* __restrict__ stab = (t == 0) ? g_P : g_O;
  const __half* __restrict__ dtab = ((t == 1) ? g_P : g_O) + 128;
  float* __restrict__ outt = out + t * EE;

  const int lane = threadIdx.x & 31;
  const int h = lane >> 4;
  const int l = lane & 15;
  const int warpId = (blockIdx.x * 256 + threadIdx.x) >> 5;
  const int W = gridDim.x * 8;

  // Per-lane second-layer weights (features l*8 .. l*8+7) in half2.
  const float4 wa = ((const float4*)w2)[l * 2];
  const float4 wb = ((const float4*)w2)[l * 2 + 1];
  const __half2 w01 = __floats2half2_rn(wa.x, wa.y);
  const __half2 w23 = __floats2half2_rn(wa.z, wa.w);
  const __half2 w45 = __floats2half2_rn(wb.x, wb.y);
  const __half2 w67 = __floats2half2_rn(wb.z, wb.w);
  const __half2 z2 = __float2half2_rn(0.f);
  const float b2v = b2[0];

  int p = warpId;
  if (p >= PT) return;
  int ei = 2 * p + h;
  int s = __ldg(idx + ei);
  int d = __ldg(idx + EE + ei);

  while (true) {
    const __half* srow = stab + (unsigned)s * 256u;
    const __half* drow = dtab + (unsigned)d * 256u;
    uint4 sa = __ldg((const uint4*)srow + l);
    uint4 da = __ldg((const uint4*)drow + l);
    int ecur = ei;

    // Prefetch next iteration's indices.
    int np = p + W;
    bool more = (np < PT);
    int ns, nd;
    if (more) {
      int nei = 2 * np + h;
      ns = __ldg(idx + nei);
      nd = __ldg(idx + EE + nei);
      ei = nei;
    }

    __half2 h0 = __hmax2(__hadd2(*(__half2*)&sa.x, *(__half2*)&da.x), z2);
    __half2 h1 = __hmax2(__hadd2(*(__half2*)&sa.y, *(__half2*)&da.y), z2);
    __half2 h2 = __hmax2(__hadd2(*(__half2*)&sa.z, *(__half2*)&da.z), z2);
    __half2 h3 = __hmax2(__hadd2(*(__half2*)&sa.w, *(__half2*)&da.w), z2);
    __half2 pa = __hfma2(h1, w23, __hmul2(h0, w01));
    __half2 pb = __hfma2(h3, w67, __hmul2(h2, w45));
    float2 fa = __half22float2(pa);
    float2 fb = __half22float2(pb);
    float acc = (fa.x + fa.y) + (fb.x + fb.y);
#pragma unroll
    for (int o = 8; o; o >>= 1) acc += __shfl_xor_sync(0xffffffffu, acc, o);
    if (l == 0) outt[ecur] = acc + b2v;

    if (!more) break;
    p = np;
    s = ns;
    d = nd;
  }
}

extern "C" void kernel_launch(void* const* d_in, const int* in_sizes, int n_in,
                              void* d_out, int out_size) {
  const float* zp = (const float*)d_in[0];
  const float* zo = (const float*)d_in[1];
  const int* e0 = (const int*)d_in[2];
  const int* e1 = (const int*)d_in[3];
  const int* e2 = (const int*)d_in[4];
  const float* w1 = (const float*)d_in[5];
  const float* b1 = (const float*)d_in[6];
  const float* w2 = (const float*)d_in[7];
  const float* b2 = (const float*)d_in[8];

  cudaFuncSetAttribute(gemm_kernel,
                       cudaFuncAttributeMaxDynamicSharedMemorySize, SMEM_TOTAL);
  gemm_kernel<<<148, 256, SMEM_TOTAL>>>(zp, zo, w1, b1);

  edge_kernel<<<dim3(400, 3), 256>>>(e0, e1, e2, w2, b2, (float*)d_out);
}